// round 1
// baseline (speedup 1.0000x reference)
#include <cuda_runtime.h>
#include <cuda_bf16.h>
#include <math.h>

// Problem constants
#define BB   4
#define HW   4096          // 64*64
#define CC   512
#define GG   32
#define CPG  16            // channels per group
#define NPIX (BB*HW)       // 16384
#define EPS  1e-5f

// ---------------- scratch (static device globals; no allocations) -------------
__device__ float g_xn [ (long)NPIX*CC ];
__device__ float g_q  [ (long)NPIX*CC ];
__device__ float g_k  [ (long)NPIX*CC ];
__device__ float g_v  [ (long)NPIX*CC ];
__device__ float g_att[ (long)NPIX*CC ];
__device__ float g_sc [ (long)BB*HW*HW ];   // 256 MB scores / attn (in-place softmax)
__device__ float g_mean[BB*GG];
__device__ float g_rstd[BB*GG];

// ---------------- GroupNorm stats: one block per (b,g) -----------------------
__global__ void gn_stats(const float* __restrict__ x,
                         float* __restrict__ meanOut, float* __restrict__ rstdOut)
{
    int bg = blockIdx.x;            // 0..127
    int b  = bg >> 5;
    int g  = bg & 31;
    const float* base = x + (long)b*HW*CC + g*CPG;
    int tid = threadIdx.x;

    float s = 0.f, ss = 0.f;
    for (int p = tid; p < HW; p += 256) {
        const float4* q4 = (const float4*)(base + (long)p*CC);
        #pragma unroll
        for (int i = 0; i < 4; i++) {
            float4 t = q4[i];
            s  += t.x + t.y + t.z + t.w;
            ss += t.x*t.x + t.y*t.y + t.z*t.z + t.w*t.w;
        }
    }
    __shared__ float rs[256], rss[256];
    rs[tid] = s; rss[tid] = ss;
    __syncthreads();
    for (int st = 128; st > 0; st >>= 1) {
        if (tid < st) { rs[tid] += rs[tid+st]; rss[tid] += rss[tid+st]; }
        __syncthreads();
    }
    if (tid == 0) {
        const float inv = 1.f / (float)(HW*CPG);
        float m   = rs[0] * inv;
        float var = rss[0] * inv - m*m;
        meanOut[bg] = m;
        rstdOut[bg] = rsqrtf(var + EPS);
    }
}

// ---------------- GroupNorm apply (vectorized) --------------------------------
__global__ void gn_apply(const float* __restrict__ x,
                         const float* __restrict__ gamma, const float* __restrict__ beta,
                         const float* __restrict__ mean,  const float* __restrict__ rstd,
                         float* __restrict__ xn)
{
    long idx = (long)blockIdx.x*256 + threadIdx.x;   // float4 index
    int  c4  = (int)(idx & 127) * 4;                 // channel of .x
    long row = idx >> 7;                             // b*HW + p
    int  b   = (int)(row >> 12);
    int  g   = c4 >> 4;
    float m = mean[b*GG + g];
    float r = rstd[b*GG + g];
    float4 xv = ((const float4*)x)[idx];
    float4 gv = ((const float4*)gamma)[c4 >> 2];
    float4 bv = ((const float4*)beta )[c4 >> 2];
    float4 o;
    o.x = (xv.x - m)*r*gv.x + bv.x;
    o.y = (xv.y - m)*r*gv.y + bv.y;
    o.z = (xv.z - m)*r*gv.z + bv.z;
    o.w = (xv.w - m)*r*gv.w + bv.w;
    ((float4*)xn)[idx] = o;
}

// ---------------- generic tiled SGEMM -----------------------------------------
// C[M,N] = scale * A[M,K] @ (TRANSB ? B[N,K]^T : B[K,N]) (+bias) (+residual)
// All of M,N divisible by 64; K divisible by 16. 16x16 threads, 4x4 microtile.
template<bool TRANSB>
__global__ void sgemm(const float* __restrict__ A, const float* __restrict__ B,
                      float* __restrict__ C,
                      int M, int N, int K,
                      long sA, long sB, long sC,
                      const float* __restrict__ bias,
                      const float* __restrict__ res, long sRes,
                      float scale)
{
    __shared__ float As[16][64];   // k-major
    __shared__ float Bs[16][64];   // k-major

    int z = blockIdx.z;
    A += sA * z;  B += sB * z;  C += sC * z;

    int bm = blockIdx.y * 64;
    int bn = blockIdx.x * 64;
    int tid = threadIdx.y * 16 + threadIdx.x;

    float acc[4][4] = {};

    for (int k0 = 0; k0 < K; k0 += 16) {
        {   // A tile: 64(m) x 16(k), float4 over k, store transposed
            int m  = tid >> 2;
            int kk = (tid & 3) * 4;
            float4 a = *(const float4*)(A + (long)(bm + m)*K + k0 + kk);
            As[kk+0][m] = a.x; As[kk+1][m] = a.y; As[kk+2][m] = a.z; As[kk+3][m] = a.w;
        }
        if (TRANSB) {   // B[N,K]: load rows (k contiguous), store transposed
            int n  = tid >> 2;
            int kk = (tid & 3) * 4;
            float4 b = *(const float4*)(B + (long)(bn + n)*K + k0 + kk);
            Bs[kk+0][n] = b.x; Bs[kk+1][n] = b.y; Bs[kk+2][n] = b.z; Bs[kk+3][n] = b.w;
        } else {        // B[K,N]: n contiguous
            int kk = tid >> 4;
            int n  = (tid & 15) * 4;
            *(float4*)&Bs[kk][n] = *(const float4*)(B + (long)(k0 + kk)*N + bn + n);
        }
        __syncthreads();

        #pragma unroll
        for (int kk = 0; kk < 16; kk++) {
            float4 a = *(float4*)&As[kk][threadIdx.y * 4];
            float4 b = *(float4*)&Bs[kk][threadIdx.x * 4];
            acc[0][0] += a.x*b.x; acc[0][1] += a.x*b.y; acc[0][2] += a.x*b.z; acc[0][3] += a.x*b.w;
            acc[1][0] += a.y*b.x; acc[1][1] += a.y*b.y; acc[1][2] += a.y*b.z; acc[1][3] += a.y*b.w;
            acc[2][0] += a.z*b.x; acc[2][1] += a.z*b.y; acc[2][2] += a.z*b.z; acc[2][3] += a.z*b.w;
            acc[3][0] += a.w*b.x; acc[3][1] += a.w*b.y; acc[3][2] += a.w*b.z; acc[3][3] += a.w*b.w;
        }
        __syncthreads();
    }

    #pragma unroll
    for (int i = 0; i < 4; i++) {
        int row = bm + threadIdx.y * 4 + i;
        #pragma unroll
        for (int j = 0; j < 4; j++) {
            int col = bn + threadIdx.x * 4 + j;
            float v = acc[i][j] * scale;
            if (bias) v += bias[col];
            if (res)  v += res[sRes * z + (long)row * N + col];
            C[(long)row * N + col] = v;
        }
    }
}

// ---------------- row softmax: one block per row of 4096 ----------------------
__global__ void softmax_rows(float* __restrict__ S)
{
    float* p = S + (long)blockIdx.x * HW;
    int tid = threadIdx.x;   // 256

    float4 v[4];
    float mx = -1e30f;
    #pragma unroll
    for (int i = 0; i < 4; i++) {
        v[i] = ((float4*)p)[tid + i * 256];
        mx = fmaxf(mx, fmaxf(fmaxf(v[i].x, v[i].y), fmaxf(v[i].z, v[i].w)));
    }
    __shared__ float red[256];
    red[tid] = mx;
    __syncthreads();
    for (int s = 128; s > 0; s >>= 1) {
        if (tid < s) red[tid] = fmaxf(red[tid], red[tid + s]);
        __syncthreads();
    }
    mx = red[0];
    __syncthreads();

    float sum = 0.f;
    #pragma unroll
    for (int i = 0; i < 4; i++) {
        v[i].x = __expf(v[i].x - mx);
        v[i].y = __expf(v[i].y - mx);
        v[i].z = __expf(v[i].z - mx);
        v[i].w = __expf(v[i].w - mx);
        sum += v[i].x + v[i].y + v[i].z + v[i].w;
    }
    red[tid] = sum;
    __syncthreads();
    for (int s = 128; s > 0; s >>= 1) {
        if (tid < s) red[tid] += red[tid + s];
        __syncthreads();
    }
    float inv = 1.f / red[0];

    #pragma unroll
    for (int i = 0; i < 4; i++) {
        v[i].x *= inv; v[i].y *= inv; v[i].z *= inv; v[i].w *= inv;
        ((float4*)p)[tid + i * 256] = v[i];
    }
}

// ---------------- host launcher ------------------------------------------------
extern "C" void kernel_launch(void* const* d_in, const int* in_sizes, int n_in,
                              void* d_out, int out_size)
{
    const float* x     = (const float*)d_in[0];
    const float* gamma = (const float*)d_in[1];
    const float* beta  = (const float*)d_in[2];
    const float* Wq    = (const float*)d_in[3];
    const float* bq    = (const float*)d_in[4];
    const float* Wk    = (const float*)d_in[5];
    const float* bk    = (const float*)d_in[6];
    const float* Wv    = (const float*)d_in[7];
    const float* bv    = (const float*)d_in[8];
    const float* Wp    = (const float*)d_in[9];
    const float* bp    = (const float*)d_in[10];
    float* out = (float*)d_out;

    static float *xn=nullptr, *q=nullptr, *k=nullptr, *v=nullptr,
                 *att=nullptr, *sc=nullptr, *mean=nullptr, *rstd=nullptr;
    if (!xn) {
        cudaGetSymbolAddress((void**)&xn,   g_xn);
        cudaGetSymbolAddress((void**)&q,    g_q);
        cudaGetSymbolAddress((void**)&k,    g_k);
        cudaGetSymbolAddress((void**)&v,    g_v);
        cudaGetSymbolAddress((void**)&att,  g_att);
        cudaGetSymbolAddress((void**)&sc,   g_sc);
        cudaGetSymbolAddress((void**)&mean, g_mean);
        cudaGetSymbolAddress((void**)&rstd, g_rstd);
    }

    const float scale = 0.044194173824159216f;  // 1/sqrt(512)
    dim3 tb(16, 16);

    // GroupNorm
    gn_stats<<<BB*GG, 256>>>(x, mean, rstd);
    gn_apply<<<(NPIX*CC/4 + 255)/256, 256>>>(x, gamma, beta, mean, rstd, xn);

    // Q, K, V projections: [16384,512] @ [512,512] + bias
    sgemm<false><<<dim3(CC/64, NPIX/64, 1), tb>>>(xn, Wq, q, NPIX, CC, CC, 0,0,0, bq, nullptr, 0, 1.f);
    sgemm<false><<<dim3(CC/64, NPIX/64, 1), tb>>>(xn, Wk, k, NPIX, CC, CC, 0,0,0, bk, nullptr, 0, 1.f);
    sgemm<false><<<dim3(CC/64, NPIX/64, 1), tb>>>(xn, Wv, v, NPIX, CC, CC, 0,0,0, bv, nullptr, 0, 1.f);

    // scores = (Q @ K^T) * scale, per-batch
    sgemm<true><<<dim3(HW/64, HW/64, BB), tb>>>(q, k, sc, HW, HW, CC,
                                               (long)HW*CC, (long)HW*CC, (long)HW*HW,
                                               nullptr, nullptr, 0, scale);

    // softmax rows
    softmax_rows<<<BB*HW, 256>>>(sc);

    // out = attn @ V, per-batch
    sgemm<false><<<dim3(CC/64, HW/64, BB), tb>>>(sc, v, att, HW, CC, HW,
                                                (long)HW*HW, (long)HW*CC, (long)HW*CC,
                                                nullptr, nullptr, 0, 1.f);

    // proj + bias + residual
    sgemm<false><<<dim3(CC/64, NPIX/64, 1), tb>>>(att, Wp, out, NPIX, CC, CC, 0,0,0,
                                                  bp, x, 0, 1.f);
}